// round 8
// baseline (speedup 1.0000x reference)
#include <cuda_runtime.h>
#include <cuda_bf16.h>
#include <math.h>
#include <stdint.h>

// ---------------- model dims ----------------
#define BS   64
#define T    96
#define C    16
#define INF_ 16
#define H    256
#define NH   8
#define DH   32
#define NCLS 4
#define L    100           // T + NCLS
#define LAYERS 4
#define M_ROWS (1024*100)  // (BS*C) * L = 102400
#define SEQS   1024        // BS*C

// ---------------- fp32 scratch ----------------
__device__ float d_h   [26214400];   // (1024,100,256)
__device__ float d_qkv [78643200];   // (1024,100,768)
__device__ float d_attn[26214400];   // attention output
__device__ float d_o   [26214400];   // gemm fp32 outputs (O-proj / FF2)
__device__ float d_tmp [104857600];  // FF1 output (1024,100,1024)
__device__ float d_a   [256];
__device__ float d_X   [1048576];
__device__ float d_H1  [1048576];
__device__ float d_H2  [1048576];
__device__ float d_d1  [16384];

// ---------------- asm helpers ----------------
__device__ __forceinline__ uint32_t smem_u32(const void* p) {
    uint32_t a;
    asm("{ .reg .u64 t; cvta.to.shared.u64 t, %1; cvt.u32.u64 %0, t; }" : "=r"(a) : "l"(p));
    return a;
}
#define CP16(s, g) asm volatile("cp.async.cg.shared.global [%0], [%1], 16;" :: "r"(s), "l"(g))
#define CP_COMMIT() asm volatile("cp.async.commit_group;")
#define CP_WAIT(n)  asm volatile("cp.async.wait_group %0;" :: "n"(n) : "memory")
#define MMA16808(c0,c1,c2,c3,a0,a1,a2,a3,b0,b1) \
    asm volatile("mma.sync.aligned.m16n8k8.row.col.f32.tf32.tf32.f32 " \
        "{%0,%1,%2,%3},{%4,%5,%6,%7},{%8,%9},{%0,%1,%2,%3};" \
        : "+f"(c0),"+f"(c1),"+f"(c2),"+f"(c3) \
        : "r"(a0),"r"(a1),"r"(a2),"r"(a3),"r"(b0),"r"(b1))

__device__ __forceinline__ uint32_t f2tf32(float x) {
    uint32_t u;
    asm("cvt.rna.tf32.f32 %0, %1;" : "=r"(u) : "f"(x));
    return u;
}

// ============================================================================
// tf32 GEMM, 2-stage cp.async pipeline.
// C(MxN) = A(MxK) @ B(NxK)^T + bias (optional relu). fp32 in/out, tf32 MMA.
// CTA 128x128, BK=64, 8 warps (2x4), warp tile 64x32.
// smem: 2 stages x 2 fp32 tiles (A,B) stride 68 floats (conflict-free frags).
// ============================================================================
#define FSTR    68
#define TILE_F  (128*FSTR)        // 8704 floats per tile
#define STAGE_F (2*TILE_F)        // 17408 floats per stage
#define GSMEM   (2*STAGE_F*4)     // 139264 bytes

__global__ __launch_bounds__(256) void k_gemm_tf32(
    const float* __restrict__ A, const float* __restrict__ B,
    const float* __restrict__ bias, float* __restrict__ Cmat,
    int M, int N, int K, int relu) {
    extern __shared__ __align__(128) float smf[];
    uint32_t sb = smem_u32(smf);

    const int tid = threadIdx.x, lane = tid & 31, wid = tid >> 5;
    const int wm = wid >> 2, wn = wid & 3;            // 2x4 warp grid
    const int gid = lane >> 2, tig = lane & 3;
    const int m0 = blockIdx.y * 128, n0 = blockIdx.x * 128;

    float acc[4][4][4];
#pragma unroll
    for (int a = 0; a < 4; a++)
#pragma unroll
        for (int b = 0; b < 4; b++)
#pragma unroll
            for (int c = 0; c < 4; c++) acc[a][b][c] = 0.f;

    const int nch = K >> 6;

    // stage one 128x64 fp32 chunk of A and B into stage s
#define STAGE_CHUNK(stg, k0)                                                   \
    do {                                                                       \
        uint32_t sA = sb + (uint32_t)((stg)*STAGE_F)*4;                        \
        uint32_t sB = sA + (uint32_t)TILE_F*4;                                 \
        _Pragma("unroll")                                                      \
        for (int i = 0; i < 8; i++) {                                          \
            int idx = tid + i * 256;      /* 0..2047 float4 slots */           \
            int r = idx >> 4, c4 = idx & 15;                                   \
            uint32_t soff = (uint32_t)(r * FSTR + c4 * 4) * 4;                 \
            CP16(sA + soff, A + (size_t)(m0 + r) * K + (k0) + c4 * 4);         \
            CP16(sB + soff, B + (size_t)(n0 + r) * K + (k0) + c4 * 4);         \
        }                                                                      \
        CP_COMMIT();                                                           \
    } while (0)

    STAGE_CHUNK(0, 0);

    for (int ch = 0; ch < nch; ch++) {
        if (ch + 1 < nch) STAGE_CHUNK((ch + 1) & 1, (ch + 1) << 6);
        if (ch + 1 < nch) CP_WAIT(1); else CP_WAIT(0);
        __syncthreads();

        const float* smA = smf + (ch & 1)*STAGE_F;
        const float* smB = smA + TILE_F;

#pragma unroll
        for (int kk = 0; kk < 8; kk++) {
            // B fragments (col-major k8 x n8): b0=[tig][gid], b1=[tig+4][gid]
            uint32_t bf[4][2];
#pragma unroll
            for (int nt = 0; nt < 4; nt++) {
                const float* bp = smB + (wn*32 + nt*8 + gid)*FSTR + kk*8 + tig;
                bf[nt][0] = f2tf32(bp[0]);
                bf[nt][1] = f2tf32(bp[4]);
            }
#pragma unroll
            for (int mt = 0; mt < 4; mt++) {
                const float* ap = smA + (wm*64 + mt*16 + gid)*FSTR + kk*8 + tig;
                uint32_t a0 = f2tf32(ap[0]);
                uint32_t a1 = f2tf32(ap[8*FSTR]);
                uint32_t a2 = f2tf32(ap[4]);
                uint32_t a3 = f2tf32(ap[8*FSTR + 4]);
#pragma unroll
                for (int nt = 0; nt < 4; nt++) {
                    MMA16808(acc[mt][nt][0], acc[mt][nt][1], acc[mt][nt][2], acc[mt][nt][3],
                             a0, a1, a2, a3, bf[nt][0], bf[nt][1]);
                }
            }
        }
        __syncthreads();
    }
#undef STAGE_CHUNK

    // epilogue (same accum layout as m16n8k16)
#pragma unroll
    for (int mt = 0; mt < 4; mt++) {
#pragma unroll
        for (int nt = 0; nt < 4; nt++) {
            int row = m0 + wm*64 + mt*16 + gid;
            int col = n0 + wn*32 + nt*8 + tig*2;
            float b0 = bias[col], b1 = bias[col + 1];
            float v00 = acc[mt][nt][0] + b0, v01 = acc[mt][nt][1] + b1;
            float v10 = acc[mt][nt][2] + b0, v11 = acc[mt][nt][3] + b1;
            if (relu) {
                v00 = fmaxf(v00, 0.f); v01 = fmaxf(v01, 0.f);
                v10 = fmaxf(v10, 0.f); v11 = fmaxf(v11, 0.f);
            }
            *reinterpret_cast<float2*>(Cmat + (size_t)row*N + col)     = make_float2(v00, v01);
            *reinterpret_cast<float2*>(Cmat + (size_t)(row+8)*N + col) = make_float2(v10, v11);
        }
    }
}

// ---------------- embedding ----------------
__global__ void k_embed(const float* __restrict__ x, const float* __restrict__ Wfc,
                        const float* __restrict__ bfc, const float* __restrict__ cls,
                        const float* __restrict__ pos, float* __restrict__ hout) {
    int r = blockIdx.x;
    int s = r / L, l = r % L;
    int b = s >> 4, c = s & 15;
    int o = threadIdx.x;
    float v;
    if (l < T) {
        const float* xr = x + (((size_t)(b*T + l))*C + c)*INF_;
        const float* wr = Wfc + o*INF_;
        float acc = bfc[o];
#pragma unroll
        for (int i = 0; i < INF_; i++) acc += xr[i]*wr[i];
        v = acc;
    } else {
        v = cls[((l - T)*C + c)*H + o];
    }
    v += pos[(l*C + c)*H + o];
    hout[(size_t)r*H + o] = v;
}

// ---------------- graph constructor ----------------
__global__ void k_graph(const float* __restrict__ emb1, const float* __restrict__ emb2,
                        const float* __restrict__ Wl1, const float* __restrict__ bl1,
                        const float* __restrict__ Wl2, const float* __restrict__ bl2,
                        float* __restrict__ a_out) {
    __shared__ float sm1[16][256];
    __shared__ float sm2[16][256];
    int o = threadIdx.x;
    for (int c = 0; c < 16; c++) {
        float s1 = bl1[o], s2 = bl2[o];
        const float* e1 = emb1 + c*256;
        const float* e2 = emb2 + c*256;
        const float* w1 = Wl1 + o*256;
        const float* w2 = Wl2 + o*256;
        for (int i = 0; i < 256; i++) { s1 += e1[i]*w1[i]; s2 += e2[i]*w2[i]; }
        sm1[c][o] = tanhf(s1); sm2[c][o] = tanhf(s2);
    }
    __syncthreads();
    int v = o >> 4, w = o & 15;
    float s = 0.f;
    for (int k = 0; k < 256; k++) s += sm1[v][k]*sm2[w][k] - sm2[v][k]*sm1[w][k];
    float adj = fmaxf(tanhf(s), 0.f) + ((v == w) ? 1.f : 0.f);
    __shared__ float sadj[256];
    __shared__ float srow[16];
    sadj[o] = adj;
    __syncthreads();
    if (o < 16) {
        float rs = 0.f;
        for (int j = 0; j < 16; j++) rs += sadj[o*16 + j];
        srow[o] = rs;
    }
    __syncthreads();
    a_out[o] = sadj[o] / srow[v];
}

// ---------------- fused attention ----------------
__global__ void k_attn(const float* __restrict__ qkv, float* __restrict__ out) {
    int hh = blockIdx.x;
    int s  = blockIdx.y;
    int tid = threadIdx.x;
    __shared__ float Ks[100][32];
    __shared__ float Vs[100][32];
    const float* base = qkv + (size_t)s*L*768;
    for (int idx = tid; idx < L*DH; idx += 128) {
        int l = idx >> 5, d = idx & 31;
        Ks[l][d] = base[l*768 + 256 + hh*DH + d];
        Vs[l][d] = base[l*768 + 512 + hh*DH + d];
    }
    __syncthreads();
    if (tid < L) {
        int lq = tid;
        float q[DH];
        const float* qp = base + lq*768 + hh*DH;
#pragma unroll
        for (int d = 0; d < DH; d++) q[d] = qp[d] * 0.17677669529663687f;
        int kmax = (lq >= T) ? L : (lq + 1);
        float m = -1e30f, sum = 0.f;
        float acc[DH];
#pragma unroll
        for (int d = 0; d < DH; d++) acc[d] = 0.f;
        for (int k = 0; k < kmax; k++) {
            float sc = 0.f;
#pragma unroll
            for (int d = 0; d < DH; d++) sc += q[d]*Ks[k][d];
            float mn = fmaxf(m, sc);
            float corr = expf(m - mn);
            float pr   = expf(sc - mn);
            sum = sum*corr + pr;
#pragma unroll
            for (int d = 0; d < DH; d++) acc[d] = acc[d]*corr + pr*Vs[k][d];
            m = mn;
        }
        float inv = 1.f/sum;
        float* op = out + ((size_t)s*L + lq)*H + hh*DH;
#pragma unroll
        for (int d = 0; d < DH; d++) op[d] = acc[d]*inv;
    }
}

// ---------------- residual add + LayerNorm (warp per row) ----------------
__global__ __launch_bounds__(256) void k_addln(
        float* __restrict__ h, const float* __restrict__ p,
        const float* __restrict__ g, const float* __restrict__ b) {
    int w = threadIdx.x >> 5, lane = threadIdx.x & 31;
    int r = blockIdx.x*8 + w;
    float4* h4 = reinterpret_cast<float4*>(h + (size_t)r*H);
    const float4* p4 = reinterpret_cast<const float4*>(p + (size_t)r*H);
    float4 v0 = h4[lane], v1 = h4[lane + 32];
    float4 q0 = p4[lane], q1 = p4[lane + 32];
    v0.x += q0.x; v0.y += q0.y; v0.z += q0.z; v0.w += q0.w;
    v1.x += q1.x; v1.y += q1.y; v1.z += q1.z; v1.w += q1.w;
    float s = v0.x + v0.y + v0.z + v0.w + v1.x + v1.y + v1.z + v1.w;
#pragma unroll
    for (int off = 16; off > 0; off >>= 1) s += __shfl_xor_sync(0xffffffffu, s, off);
    float mean = s * (1.f/H);
    float d0x = v0.x-mean, d0y = v0.y-mean, d0z = v0.z-mean, d0w = v0.w-mean;
    float d1x = v1.x-mean, d1y = v1.y-mean, d1z = v1.z-mean, d1w = v1.w-mean;
    float vs = d0x*d0x + d0y*d0y + d0z*d0z + d0w*d0w
             + d1x*d1x + d1y*d1y + d1z*d1z + d1w*d1w;
#pragma unroll
    for (int off = 16; off > 0; off >>= 1) vs += __shfl_xor_sync(0xffffffffu, vs, off);
    float rstd = rsqrtf(vs * (1.f/H) + 1e-5f);
    const float4* g4 = reinterpret_cast<const float4*>(g);
    const float4* b4 = reinterpret_cast<const float4*>(b);
    float4 ga = g4[lane], gb = g4[lane + 32];
    float4 ba = b4[lane], bb = b4[lane + 32];
    float4 o0, o1;
    o0.x = d0x*rstd*ga.x + ba.x; o0.y = d0y*rstd*ga.y + ba.y;
    o0.z = d0z*rstd*ga.z + ba.z; o0.w = d0w*rstd*ga.w + ba.w;
    o1.x = d1x*rstd*gb.x + bb.x; o1.y = d1y*rstd*gb.y + bb.y;
    o1.z = d1z*rstd*gb.z + bb.z; o1.w = d1w*rstd*gb.w + bb.w;
    h4[lane] = o0; h4[lane + 32] = o1;
}

// ---------------- mixprop pieces ----------------
__global__ void k_extract(const float* __restrict__ h, float* __restrict__ X) {
    int b = blockIdx.x;
    int ch = threadIdx.x;
    int lc = b & 3, sw = b >> 2;
    X[(size_t)b*H + ch] = h[(size_t)sw*(L*H) + (T + lc)*H + ch];
}

__global__ void k_prop(const float* __restrict__ a, const float* __restrict__ in,
                       float* __restrict__ out) {
    __shared__ float sa[256];
    int tid = threadIdx.x;
    sa[tid] = a[tid];
    __syncthreads();
    int b = blockIdx.x;
    int lc = b & 3, v = (b >> 2) & 15, n = b >> 6;
    float acc = 0.f;
#pragma unroll
    for (int w = 0; w < 16; w++)
        acc += sa[v*16 + w] * in[((size_t)(n*16 + w)*4 + lc)*H + tid];
    out[(size_t)b*H + tid] = acc;
}

__global__ void k_mixout(const float* __restrict__ X, const float* __restrict__ H1,
                         const float* __restrict__ H2, const float* __restrict__ Wm,
                         const float* __restrict__ bm, float* __restrict__ h) {
    __shared__ float row[768];
    int b = blockIdx.x, o = threadIdx.x;
    row[o]       = X [(size_t)b*H + o];
    row[256 + o] = H1[(size_t)b*H + o];
    row[512 + o] = H2[(size_t)b*H + o];
    __syncthreads();
    const float* wr = Wm + (size_t)o*768;
    float acc = bm[o];
    for (int ch = 0; ch < 768; ch++) acc += wr[ch]*row[ch];
    int lc = b & 3, sw = b >> 2;
    h[(size_t)sw*(L*H) + (T + lc)*H + o] = acc;
}

// ---------------- decoder ----------------
__global__ void k_dec1(const float* __restrict__ h, const float* __restrict__ Wd1,
                       const float* __restrict__ bd1, float* __restrict__ d1) {
    __shared__ float zc[1024];
    int n = blockIdx.x, o = threadIdx.x;
    float acc = 0.f;
    for (int c = 0; c < 16; c++) {
        const float* hp = h + (size_t)(n*16 + c)*(L*H) + T*H;
        for (int jj = o; jj < 1024; jj += 256) zc[jj] = tanhf(hp[jj]);
        __syncthreads();
        const float* wr = Wd1 + (size_t)o*16384 + c*1024;
        float a = 0.f;
        for (int jj = 0; jj < 1024; jj++) a += wr[jj]*zc[jj];
        acc += a;
        __syncthreads();
    }
    acc += bd1[o];
    d1[n*H + o] = 0.5f*acc*(1.f + erff(acc*0.70710678118654752f));
}

__global__ void k_dec2(const float* __restrict__ d1, const float* __restrict__ Wd2,
                       const float* __restrict__ bd2, float* __restrict__ out) {
    int n = blockIdx.x, tid = threadIdx.x;
    float v = d1[n*H + tid]*Wd2[tid];
    __shared__ float red[8];
#pragma unroll
    for (int off = 16; off > 0; off >>= 1) v += __shfl_down_sync(0xffffffffu, v, off);
    if ((tid & 31) == 0) red[tid >> 5] = v;
    __syncthreads();
    if (tid == 0) {
        float s = 0.f;
        for (int i = 0; i < 8; i++) s += red[i];
        out[n] = s + bd2[0];
    }
}

// ---------------- launch ----------------
extern "C" void kernel_launch(void* const* d_in, const int* in_sizes, int n_in,
                              void* d_out, int out_size) {
    const float* x        = (const float*)d_in[0];
    const float* Wfc      = (const float*)d_in[3];
    const float* bfc      = (const float*)d_in[4];
    const float* cls_tok  = (const float*)d_in[5];
    const float* pos_emb  = (const float*)d_in[6];
    const float* emb1     = (const float*)d_in[7];
    const float* emb2     = (const float*)d_in[8];
    const float* Wl1      = (const float*)d_in[9];
    const float* bl1      = (const float*)d_in[10];
    const float* Wl2      = (const float*)d_in[11];
    const float* bl2      = (const float*)d_in[12];
    const float* Wqkv     = (const float*)d_in[13];
    const float* bqkv     = (const float*)d_in[14];
    const float* Wo       = (const float*)d_in[15];
    const float* bo       = (const float*)d_in[16];
    const float* W1       = (const float*)d_in[17];
    const float* b1       = (const float*)d_in[18];
    const float* W2       = (const float*)d_in[19];
    const float* b2       = (const float*)d_in[20];
    const float* ln1g     = (const float*)d_in[21];
    const float* ln1b     = (const float*)d_in[22];
    const float* ln2g     = (const float*)d_in[23];
    const float* ln2b     = (const float*)d_in[24];
    const float* Wmlp     = (const float*)d_in[25];
    const float* bmlp     = (const float*)d_in[26];
    const float* Wd1      = (const float*)d_in[27];
    const float* bd1      = (const float*)d_in[28];
    const float* Wd2      = (const float*)d_in[29];
    const float* bd2      = (const float*)d_in[30];
    float* out = (float*)d_out;

    float *p_h, *p_qkv, *p_attn, *p_o, *p_tmp, *p_a, *p_X, *p_H1, *p_H2, *p_d1;
    cudaGetSymbolAddress((void**)&p_h,    d_h);
    cudaGetSymbolAddress((void**)&p_qkv,  d_qkv);
    cudaGetSymbolAddress((void**)&p_attn, d_attn);
    cudaGetSymbolAddress((void**)&p_o,    d_o);
    cudaGetSymbolAddress((void**)&p_tmp,  d_tmp);
    cudaGetSymbolAddress((void**)&p_a,    d_a);
    cudaGetSymbolAddress((void**)&p_X,    d_X);
    cudaGetSymbolAddress((void**)&p_H1,   d_H1);
    cudaGetSymbolAddress((void**)&p_H2,   d_H2);
    cudaGetSymbolAddress((void**)&p_d1,   d_d1);

    cudaFuncSetAttribute(k_gemm_tf32, cudaFuncAttributeMaxDynamicSharedMemorySize, GSMEM);

    // embedding + graph
    k_embed<<<M_ROWS, 256>>>(x, Wfc, bfc, cls_tok, pos_emb, p_h);
    k_graph<<<1, 256>>>(emb1, emb2, Wl1, bl1, Wl2, bl2, p_a);

    for (int l = 0; l < LAYERS; l++) {
        if (l > 0) {
            k_extract<<<4096, 256>>>(p_h, p_X);
            k_prop<<<4096, 256>>>(p_a, p_X,  p_H1);
            k_prop<<<4096, 256>>>(p_a, p_H1, p_H2);
            k_mixout<<<4096, 256>>>(p_X, p_H1, p_H2,
                                    Wmlp + (size_t)(l-1)*256*768, bmlp + (l-1)*256, p_h);
        }
        // QKV
        k_gemm_tf32<<<dim3(768/128, M_ROWS/128), 256, GSMEM>>>(
            p_h, Wqkv + (size_t)l*768*256, bqkv + l*768, p_qkv, M_ROWS, 768, 256, 0);
        // attention
        k_attn<<<dim3(NH, SEQS), 128>>>(p_qkv, p_attn);
        // O-proj
        k_gemm_tf32<<<dim3(256/128, M_ROWS/128), 256, GSMEM>>>(
            p_attn, Wo + (size_t)l*256*256, bo + l*256, p_o, M_ROWS, 256, 256, 0);
        k_addln<<<M_ROWS/8, 256>>>(p_h, p_o, ln1g + l*256, ln1b + l*256);
        // FF1 (relu)
        k_gemm_tf32<<<dim3(1024/128, M_ROWS/128), 256, GSMEM>>>(
            p_h, W1 + (size_t)l*1024*256, b1 + l*1024, p_tmp, M_ROWS, 1024, 256, 1);
        // FF2
        k_gemm_tf32<<<dim3(256/128, M_ROWS/128), 256, GSMEM>>>(
            p_tmp, W2 + (size_t)l*256*1024, b2 + l*256, p_o, M_ROWS, 256, 1024, 0);
        k_addln<<<M_ROWS/8, 256>>>(p_h, p_o, ln2g + l*256, ln2b + l*256);
    }

    // decoder
    k_dec1<<<BS, 256>>>(p_h, Wd1, bd1, p_d1);
    k_dec2<<<BS, 256>>>(p_d1, Wd2, bd2, out);
}

// round 9
// speedup vs baseline: 1.6503x; 1.6503x over previous
#include <cuda_runtime.h>
#include <cuda_bf16.h>
#include <math.h>
#include <stdint.h>

// ---------------- model dims ----------------
#define BS   64
#define T    96
#define C    16
#define INF_ 16
#define H    256
#define NH   8
#define DH   32
#define NCLS 4
#define L    100           // T + NCLS
#define LAYERS 4
#define M_ROWS (1024*100)  // (BS*C) * L = 102400
#define SEQS   1024        // BS*C

// ---------------- fp32 scratch ----------------
__device__ float d_h   [26214400];   // (1024,100,256)  (tf32-rounded values)
__device__ float d_qkv [78643200];   // (1024,100,768)  full fp32
__device__ float d_attn[26214400];   // attention output (tf32-rounded)
__device__ float d_o   [26214400];   // O-proj / FF2 fp32 outputs
__device__ float d_tmp [104857600];  // FF1 output (tf32-rounded)
__device__ float d_a   [256];
__device__ float d_X   [1048576];
__device__ float d_H1  [1048576];
__device__ float d_H2  [1048576];
__device__ float d_d1  [16384];
// tf32-rounded weights
__device__ float d_wq [786432];
__device__ float d_wo [262144];
__device__ float d_w1 [1048576];
__device__ float d_w2 [1048576];

// ---------------- asm helpers ----------------
__device__ __forceinline__ uint32_t smem_u32(const void* p) {
    uint32_t a;
    asm("{ .reg .u64 t; cvta.to.shared.u64 t, %1; cvt.u32.u64 %0, t; }" : "=r"(a) : "l"(p));
    return a;
}
#define CP16(s, g) asm volatile("cp.async.cg.shared.global [%0], [%1], 16;" :: "r"(s), "l"(g))
#define CP_COMMIT() asm volatile("cp.async.commit_group;")
#define CP_WAIT(n)  asm volatile("cp.async.wait_group %0;" :: "n"(n) : "memory")
#define LDSM_X4(r0,r1,r2,r3,addr) \
    asm volatile("ldmatrix.sync.aligned.m8n8.x4.shared.b16 {%0,%1,%2,%3}, [%4];" \
        : "=r"(r0),"=r"(r1),"=r"(r2),"=r"(r3) : "r"(addr))
#define LDSM_X2(r0,r1,addr) \
    asm volatile("ldmatrix.sync.aligned.m8n8.x2.shared.b16 {%0,%1}, [%2];" \
        : "=r"(r0),"=r"(r1) : "r"(addr))
#define MMA16808(c0,c1,c2,c3,a0,a1,a2,a3,b0,b1) \
    asm volatile("mma.sync.aligned.m16n8k8.row.col.f32.tf32.tf32.f32 " \
        "{%0,%1,%2,%3},{%4,%5,%6,%7},{%8,%9},{%0,%1,%2,%3};" \
        : "+f"(c0),"+f"(c1),"+f"(c2),"+f"(c3) \
        : "r"(a0),"r"(a1),"r"(a2),"r"(a3),"r"(b0),"r"(b1))

// round-to-nearest tf32, returned as fp32 bit pattern
__device__ __forceinline__ float tf32r(float x) {
    uint32_t u;
    asm("cvt.rna.tf32.f32 %0, %1;" : "=r"(u) : "f"(x));
    return __uint_as_float(u);
}

// ============================================================================
// tf32 GEMM: C(MxN) = A(MxK) @ B(NxK)^T + bias (opt relu / tf32-round output)
// Operands MUST be pre-rounded to tf32 (bit-pattern fp32).
// CTA 128x128, BK=64, 8 warps (2x4), warp tile 64x32, 2-stage cp.async.
// smem fp32 tiles stride 68 floats; ldmatrix on b16 view (tf32 frag trick).
// ============================================================================
#define FSTR    68
#define TILE_F  (128*FSTR)        // floats
#define STAGE_F (2*TILE_F)
#define GSMEM   (2*STAGE_F*4)     // 139264 bytes

__global__ __launch_bounds__(256) void k_gemm_tf32(
    const float* __restrict__ A, const float* __restrict__ B,
    const float* __restrict__ bias, float* __restrict__ Cmat,
    int M, int N, int K, int relu, int roundC) {
    extern __shared__ __align__(128) float smf[];
    uint32_t sb = smem_u32(smf);

    const int tid = threadIdx.x, lane = tid & 31, wid = tid >> 5;
    const int wm = wid >> 2, wn = wid & 3;            // 2x4 warp grid
    const int gid = lane >> 2, tig = lane & 3;
    const int m0 = blockIdx.y * 128, n0 = blockIdx.x * 128;

    float acc[4][4][4];
#pragma unroll
    for (int a = 0; a < 4; a++)
#pragma unroll
        for (int b = 0; b < 4; b++)
#pragma unroll
            for (int c = 0; c < 4; c++) acc[a][b][c] = 0.f;

    // ldmatrix lane-relative byte offsets within a tile
    const uint32_t a_row = (uint32_t)(lane & 15);          // 16 rows
    const uint32_t a_cg  = (uint32_t)((lane >> 4) * 16);   // 8 b16 = 16 bytes
    const uint32_t b_row = (uint32_t)(lane & 7);
    const uint32_t b_cg  = (uint32_t)(((lane >> 3) & 1) * 16);

    const int nch = K >> 6;

#define STAGE_CHUNK(stg, k0)                                                   \
    do {                                                                       \
        uint32_t sA = sb + (uint32_t)((stg)*STAGE_F)*4;                        \
        uint32_t sB = sA + (uint32_t)TILE_F*4;                                 \
        _Pragma("unroll")                                                      \
        for (int i = 0; i < 8; i++) {                                          \
            int idx = tid + i * 256;      /* 0..2047 float4 slots */           \
            int r = idx >> 4, c4 = idx & 15;                                   \
            uint32_t soff = (uint32_t)(r * FSTR + c4 * 4) * 4;                 \
            CP16(sA + soff, A + (size_t)(m0 + r) * K + (k0) + c4 * 4);         \
            CP16(sB + soff, B + (size_t)(n0 + r) * K + (k0) + c4 * 4);         \
        }                                                                      \
        CP_COMMIT();                                                           \
    } while (0)

    STAGE_CHUNK(0, 0);

    for (int ch = 0; ch < nch; ch++) {
        if (ch + 1 < nch) STAGE_CHUNK((ch + 1) & 1, (ch + 1) << 6);
        if (ch + 1 < nch) CP_WAIT(1); else CP_WAIT(0);
        __syncthreads();

        uint32_t sA = sb + (uint32_t)((ch & 1)*STAGE_F)*4;
        uint32_t sB = sA + (uint32_t)TILE_F*4;

#pragma unroll
        for (int kk = 0; kk < 8; kk++) {
            // B fragments: 8 n-rows x 8 tf32-k region via ldmatrix.x2 (b16 view)
            uint32_t bf[4][2];
#pragma unroll
            for (int nt = 0; nt < 4; nt++) {
                uint32_t addr = sB + (uint32_t)(wn*32 + nt*8 + b_row)*(FSTR*4)
                                   + (uint32_t)kk*32 + b_cg;
                LDSM_X2(bf[nt][0], bf[nt][1], addr);
            }
#pragma unroll
            for (int mt = 0; mt < 4; mt++) {
                uint32_t addr = sA + (uint32_t)(wm*64 + mt*16 + a_row)*(FSTR*4)
                                   + (uint32_t)kk*32 + a_cg;
                uint32_t a0, a1, a2, a3;
                LDSM_X4(a0, a1, a2, a3, addr);
#pragma unroll
                for (int nt = 0; nt < 4; nt++) {
                    MMA16808(acc[mt][nt][0], acc[mt][nt][1], acc[mt][nt][2], acc[mt][nt][3],
                             a0, a1, a2, a3, bf[nt][0], bf[nt][1]);
                }
            }
        }
        __syncthreads();
    }
#undef STAGE_CHUNK

    // epilogue
#pragma unroll
    for (int mt = 0; mt < 4; mt++) {
#pragma unroll
        for (int nt = 0; nt < 4; nt++) {
            int row = m0 + wm*64 + mt*16 + gid;
            int col = n0 + wn*32 + nt*8 + tig*2;
            float b0 = bias[col], b1 = bias[col + 1];
            float v00 = acc[mt][nt][0] + b0, v01 = acc[mt][nt][1] + b1;
            float v10 = acc[mt][nt][2] + b0, v11 = acc[mt][nt][3] + b1;
            if (relu) {
                v00 = fmaxf(v00, 0.f); v01 = fmaxf(v01, 0.f);
                v10 = fmaxf(v10, 0.f); v11 = fmaxf(v11, 0.f);
            }
            if (roundC) {
                v00 = tf32r(v00); v01 = tf32r(v01);
                v10 = tf32r(v10); v11 = tf32r(v11);
            }
            *reinterpret_cast<float2*>(Cmat + (size_t)row*N + col)     = make_float2(v00, v01);
            *reinterpret_cast<float2*>(Cmat + (size_t)(row+8)*N + col) = make_float2(v10, v11);
        }
    }
}

// ---------------- weight tf32 rounding ----------------
__global__ void k_round(const float* __restrict__ in, float* __restrict__ outp, int n) {
    int i = blockIdx.x*256 + threadIdx.x;
    if (i < n) outp[i] = tf32r(in[i]);
}

// ---------------- embedding (tf32-rounded output) ----------------
__global__ void k_embed(const float* __restrict__ x, const float* __restrict__ Wfc,
                        const float* __restrict__ bfc, const float* __restrict__ cls,
                        const float* __restrict__ pos, float* __restrict__ hout) {
    int r = blockIdx.x;
    int s = r / L, l = r % L;
    int b = s >> 4, c = s & 15;
    int o = threadIdx.x;
    float v;
    if (l < T) {
        const float* xr = x + (((size_t)(b*T + l))*C + c)*INF_;
        const float* wr = Wfc + o*INF_;
        float acc = bfc[o];
#pragma unroll
        for (int i = 0; i < INF_; i++) acc += xr[i]*wr[i];
        v = acc;
    } else {
        v = cls[((l - T)*C + c)*H + o];
    }
    v += pos[(l*C + c)*H + o];
    hout[(size_t)r*H + o] = tf32r(v);
}

// ---------------- graph constructor ----------------
__global__ void k_graph(const float* __restrict__ emb1, const float* __restrict__ emb2,
                        const float* __restrict__ Wl1, const float* __restrict__ bl1,
                        const float* __restrict__ Wl2, const float* __restrict__ bl2,
                        float* __restrict__ a_out) {
    __shared__ float sm1[16][256];
    __shared__ float sm2[16][256];
    int o = threadIdx.x;
    for (int c = 0; c < 16; c++) {
        float s1 = bl1[o], s2 = bl2[o];
        const float* e1 = emb1 + c*256;
        const float* e2 = emb2 + c*256;
        const float* w1 = Wl1 + o*256;
        const float* w2 = Wl2 + o*256;
        for (int i = 0; i < 256; i++) { s1 += e1[i]*w1[i]; s2 += e2[i]*w2[i]; }
        sm1[c][o] = tanhf(s1); sm2[c][o] = tanhf(s2);
    }
    __syncthreads();
    int v = o >> 4, w = o & 15;
    float s = 0.f;
    for (int k = 0; k < 256; k++) s += sm1[v][k]*sm2[w][k] - sm2[v][k]*sm1[w][k];
    float adj = fmaxf(tanhf(s), 0.f) + ((v == w) ? 1.f : 0.f);
    __shared__ float sadj[256];
    __shared__ float srow[16];
    sadj[o] = adj;
    __syncthreads();
    if (o < 16) {
        float rs = 0.f;
        for (int j = 0; j < 16; j++) rs += sadj[o*16 + j];
        srow[o] = rs;
    }
    __syncthreads();
    a_out[o] = sadj[o] / srow[v];
}

// ---------------- fused attention (tf32-rounded output) ----------------
__global__ void k_attn(const float* __restrict__ qkv, float* __restrict__ out) {
    int hh = blockIdx.x;
    int s  = blockIdx.y;
    int tid = threadIdx.x;
    __shared__ float Ks[100][32];
    __shared__ float Vs[100][32];
    const float* base = qkv + (size_t)s*L*768;
    for (int idx = tid; idx < L*DH; idx += 128) {
        int l = idx >> 5, d = idx & 31;
        Ks[l][d] = base[l*768 + 256 + hh*DH + d];
        Vs[l][d] = base[l*768 + 512 + hh*DH + d];
    }
    __syncthreads();
    if (tid < L) {
        int lq = tid;
        float q[DH];
        const float* qp = base + lq*768 + hh*DH;
#pragma unroll
        for (int d = 0; d < DH; d++) q[d] = qp[d] * 0.17677669529663687f;
        int kmax = (lq >= T) ? L : (lq + 1);
        float m = -1e30f, sum = 0.f;
        float acc[DH];
#pragma unroll
        for (int d = 0; d < DH; d++) acc[d] = 0.f;
        for (int k = 0; k < kmax; k++) {
            float sc = 0.f;
#pragma unroll
            for (int d = 0; d < DH; d++) sc += q[d]*Ks[k][d];
            float mn = fmaxf(m, sc);
            float corr = expf(m - mn);
            float pr   = expf(sc - mn);
            sum = sum*corr + pr;
#pragma unroll
            for (int d = 0; d < DH; d++) acc[d] = acc[d]*corr + pr*Vs[k][d];
            m = mn;
        }
        float inv = 1.f/sum;
        float* op = out + ((size_t)s*L + lq)*H + hh*DH;
#pragma unroll
        for (int d = 0; d < DH; d++) op[d] = tf32r(acc[d]*inv);
    }
}

// ---------------- residual add + LayerNorm (warp per row, tf32-rounded h) ----
__global__ __launch_bounds__(256) void k_addln(
        float* __restrict__ h, const float* __restrict__ p,
        const float* __restrict__ g, const float* __restrict__ b) {
    int w = threadIdx.x >> 5, lane = threadIdx.x & 31;
    int r = blockIdx.x*8 + w;
    float4* h4 = reinterpret_cast<float4*>(h + (size_t)r*H);
    const float4* p4 = reinterpret_cast<const float4*>(p + (size_t)r*H);
    float4 v0 = h4[lane], v1 = h4[lane + 32];
    float4 q0 = p4[lane], q1 = p4[lane + 32];
    v0.x += q0.x; v0.y += q0.y; v0.z += q0.z; v0.w += q0.w;
    v1.x += q1.x; v1.y += q1.y; v1.z += q1.z; v1.w += q1.w;
    float s = v0.x + v0.y + v0.z + v0.w + v1.x + v1.y + v1.z + v1.w;
#pragma unroll
    for (int off = 16; off > 0; off >>= 1) s += __shfl_xor_sync(0xffffffffu, s, off);
    float mean = s * (1.f/H);
    float d0x = v0.x-mean, d0y = v0.y-mean, d0z = v0.z-mean, d0w = v0.w-mean;
    float d1x = v1.x-mean, d1y = v1.y-mean, d1z = v1.z-mean, d1w = v1.w-mean;
    float vs = d0x*d0x + d0y*d0y + d0z*d0z + d0w*d0w
             + d1x*d1x + d1y*d1y + d1z*d1z + d1w*d1w;
#pragma unroll
    for (int off = 16; off > 0; off >>= 1) vs += __shfl_xor_sync(0xffffffffu, vs, off);
    float rstd = rsqrtf(vs * (1.f/H) + 1e-5f);
    const float4* g4 = reinterpret_cast<const float4*>(g);
    const float4* b4 = reinterpret_cast<const float4*>(b);
    float4 ga = g4[lane], gb = g4[lane + 32];
    float4 ba = b4[lane], bb = b4[lane + 32];
    float4 o0, o1;
    o0.x = tf32r(d0x*rstd*ga.x + ba.x); o0.y = tf32r(d0y*rstd*ga.y + ba.y);
    o0.z = tf32r(d0z*rstd*ga.z + ba.z); o0.w = tf32r(d0w*rstd*ga.w + ba.w);
    o1.x = tf32r(d1x*rstd*gb.x + bb.x); o1.y = tf32r(d1y*rstd*gb.y + bb.y);
    o1.z = tf32r(d1z*rstd*gb.z + bb.z); o1.w = tf32r(d1w*rstd*gb.w + bb.w);
    h4[lane] = o0; h4[lane + 32] = o1;
}

// ---------------- mixprop pieces ----------------
__global__ void k_extract(const float* __restrict__ h, float* __restrict__ X) {
    int b = blockIdx.x;
    int ch = threadIdx.x;
    int lc = b & 3, sw = b >> 2;
    X[(size_t)b*H + ch] = h[(size_t)sw*(L*H) + (T + lc)*H + ch];
}

__global__ void k_prop(const float* __restrict__ a, const float* __restrict__ in,
                       float* __restrict__ out) {
    __shared__ float sa[256];
    int tid = threadIdx.x;
    sa[tid] = a[tid];
    __syncthreads();
    int b = blockIdx.x;
    int lc = b & 3, v = (b >> 2) & 15, n = b >> 6;
    float acc = 0.f;
#pragma unroll
    for (int w = 0; w < 16; w++)
        acc += sa[v*16 + w] * in[((size_t)(n*16 + w)*4 + lc)*H + tid];
    out[(size_t)b*H + tid] = acc;
}

__global__ void k_mixout(const float* __restrict__ X, const float* __restrict__ H1,
                         const float* __restrict__ H2, const float* __restrict__ Wm,
                         const float* __restrict__ bm, float* __restrict__ h) {
    __shared__ float row[768];
    int b = blockIdx.x, o = threadIdx.x;
    row[o]       = X [(size_t)b*H + o];
    row[256 + o] = H1[(size_t)b*H + o];
    row[512 + o] = H2[(size_t)b*H + o];
    __syncthreads();
    const float* wr = Wm + (size_t)o*768;
    float acc = bm[o];
    for (int ch = 0; ch < 768; ch++) acc += wr[ch]*row[ch];
    int lc = b & 3, sw = b >> 2;
    h[(size_t)sw*(L*H) + (T + lc)*H + o] = tf32r(acc);
}

// ---------------- decoder ----------------
__global__ void k_dec1(const float* __restrict__ h, const float* __restrict__ Wd1,
                       const float* __restrict__ bd1, float* __restrict__ d1) {
    __shared__ float zc[1024];
    int n = blockIdx.x, o = threadIdx.x;
    float acc = 0.f;
    for (int c = 0; c < 16; c++) {
        const float* hp = h + (size_t)(n*16 + c)*(L*H) + T*H;
        for (int jj = o; jj < 1024; jj += 256) zc[jj] = tanhf(hp[jj]);
        __syncthreads();
        const float* wr = Wd1 + (size_t)o*16384 + c*1024;
        float a = 0.f;
        for (int jj = 0; jj < 1024; jj++) a += wr[jj]*zc[jj];
        acc += a;
        __syncthreads();
    }
    acc += bd1[o];
    d1[n*H + o] = 0.5f*acc*(1.f + erff(acc*0.70710678118654752f));
}

__global__ void k_dec2(const float* __restrict__ d1, const float* __restrict__ Wd2,
                       const float* __restrict__ bd2, float* __restrict__ out) {
    int n = blockIdx.x, tid = threadIdx.x;
    float v = d1[n*H + tid]*Wd2[tid];
    __shared__ float red[8];
#pragma unroll
    for (int off = 16; off > 0; off >>= 1) v += __shfl_down_sync(0xffffffffu, v, off);
    if ((tid & 31) == 0) red[tid >> 5] = v;
    __syncthreads();
    if (tid == 0) {
        float s = 0.f;
        for (int i = 0; i < 8; i++) s += red[i];
        out[n] = s + bd2[0];
    }
}

// ---------------- launch ----------------
extern "C" void kernel_launch(void* const* d_in, const int* in_sizes, int n_in,
                              void* d_out, int out_size) {
    const float* x        = (const float*)d_in[0];
    const float* Wfc      = (const float*)d_in[3];
    const float* bfc      = (const float*)d_in[4];
    const float* cls_tok  = (const float*)d_in[5];
    const float* pos_emb  = (const float*)d_in[6];
    const float* emb1     = (const float*)d_in[7];
    const float* emb2     = (const float*)d_in[8];
    const float* Wl1      = (const float*)d_in[9];
    const float* bl1      = (const float*)d_in[10];
    const float* Wl2      = (const float*)d_in[11];
    const float* bl2      = (const float*)d_in[12];
    const float* Wqkv     = (const float*)d_in[13];
    const float* bqkv     = (const float*)d_in[14];
    const float* Wo       = (const float*)d_in[15];
    const float* bo       = (const float*)d_in[16];
    const float* W1       = (const float*)d_in[17];
    const float* b1       = (const float*)d_in[18];
    const float* W2       = (const float*)d_in[19];
    const float* b2       = (const float*)d_in[20];
    const float* ln1g     = (const float*)d_in[21];
    const float* ln1b     = (const float*)d_in[22];
    const float* ln2g     = (const float*)d_in[23];
    const float* ln2b     = (const float*)d_in[24];
    const float* Wmlp     = (const float*)d_in[25];
    const float* bmlp     = (const float*)d_in[26];
    const float* Wd1      = (const float*)d_in[27];
    const float* bd1      = (const float*)d_in[28];
    const float* Wd2      = (const float*)d_in[29];
    const float* bd2      = (const float*)d_in[30];
    float* out = (float*)d_out;

    float *p_h, *p_qkv, *p_attn, *p_o, *p_tmp, *p_a, *p_X, *p_H1, *p_H2, *p_d1;
    float *p_wq, *p_wo, *p_w1, *p_w2;
    cudaGetSymbolAddress((void**)&p_h,    d_h);
    cudaGetSymbolAddress((void**)&p_qkv,  d_qkv);
    cudaGetSymbolAddress((void**)&p_attn, d_attn);
    cudaGetSymbolAddress((void**)&p_o,    d_o);
    cudaGetSymbolAddress((void**)&p_tmp,  d_tmp);
    cudaGetSymbolAddress((void**)&p_a,    d_a);
    cudaGetSymbolAddress((void**)&p_X,    d_X);
    cudaGetSymbolAddress((void**)&p_H1,   d_H1);
    cudaGetSymbolAddress((void**)&p_H2,   d_H2);
    cudaGetSymbolAddress((void**)&p_d1,   d_d1);
    cudaGetSymbolAddress((void**)&p_wq,   d_wq);
    cudaGetSymbolAddress((void**)&p_wo,   d_wo);
    cudaGetSymbolAddress((void**)&p_w1,   d_w1);
    cudaGetSymbolAddress((void**)&p_w2,   d_w2);

    cudaFuncSetAttribute(k_gemm_tf32, cudaFuncAttributeMaxDynamicSharedMemorySize, GSMEM);

    // tf32-round weights once
    k_round<<<(786432 + 255)/256, 256>>>(Wqkv, p_wq, 786432);
    k_round<<<(262144 + 255)/256, 256>>>(Wo,   p_wo, 262144);
    k_round<<<(1048576 + 255)/256, 256>>>(W1,  p_w1, 1048576);
    k_round<<<(1048576 + 255)/256, 256>>>(W2,  p_w2, 1048576);

    // embedding + graph
    k_embed<<<M_ROWS, 256>>>(x, Wfc, bfc, cls_tok, pos_emb, p_h);
    k_graph<<<1, 256>>>(emb1, emb2, Wl1, bl1, Wl2, bl2, p_a);

    for (int l = 0; l < LAYERS; l++) {
        if (l > 0) {
            k_extract<<<4096, 256>>>(p_h, p_X);
            k_prop<<<4096, 256>>>(p_a, p_X,  p_H1);
            k_prop<<<4096, 256>>>(p_a, p_H1, p_H2);
            k_mixout<<<4096, 256>>>(p_X, p_H1, p_H2,
                                    Wmlp + (size_t)(l-1)*256*768, bmlp + (l-1)*256, p_h);
        }
        // QKV (full fp32 output for softmax)
        k_gemm_tf32<<<dim3(768/128, M_ROWS/128), 256, GSMEM>>>(
            p_h, p_wq + (size_t)l*768*256, bqkv + l*768, p_qkv, M_ROWS, 768, 256, 0, 0);
        // attention
        k_attn<<<dim3(NH, SEQS), 128>>>(p_qkv, p_attn);
        // O-proj (fp32 output -> addln)
        k_gemm_tf32<<<dim3(256/128, M_ROWS/128), 256, GSMEM>>>(
            p_attn, p_wo + (size_t)l*256*256, bo + l*256, p_o, M_ROWS, 256, 256, 0, 0);
        k_addln<<<M_ROWS/8, 256>>>(p_h, p_o, ln1g + l*256, ln1b + l*256);
        // FF1 (relu, tf32-rounded output -> FF2 GEMM)
        k_gemm_tf32<<<dim3(1024/128, M_ROWS/128), 256, GSMEM>>>(
            p_h, p_w1 + (size_t)l*1024*256, b1 + l*1024, p_tmp, M_ROWS, 1024, 256, 1, 1);
        // FF2 (fp32 output -> addln)
        k_gemm_tf32<<<dim3(256/128, M_ROWS/128), 256, GSMEM>>>(
            p_tmp, p_w2 + (size_t)l*256*1024, b2 + l*256, p_o, M_ROWS, 256, 1024, 0, 0);
        k_addln<<<M_ROWS/8, 256>>>(p_h, p_o, ln2g + l*256, ln2b + l*256);
    }

    // decoder
    k_dec1<<<BS, 256>>>(p_h, Wd1, bd1, p_d1);
    k_dec2<<<BS, 256>>>(p_d1, Wd2, bd2, out);
}

// round 10
// speedup vs baseline: 1.8260x; 1.1065x over previous
#include <cuda_runtime.h>
#include <cuda_fp16.h>
#include <math.h>
#include <stdint.h>

// ---------------- model dims ----------------
#define BS   64
#define T    96
#define C    16
#define INF_ 16
#define H    256
#define NH   8
#define DH   32
#define NCLS 4
#define L    100           // T + NCLS
#define LAYERS 4
#define M_ROWS (1024*100)  // (BS*C) * L = 102400
#define SEQS   1024        // BS*C

// ---------------- fp32 scratch ----------------
__device__ float d_h   [26214400];   // (1024,100,256) residual master
__device__ float d_qkv [78643200];   // (1024,100,768)
__device__ float d_o   [26214400];   // O-proj / FF2 fp32 outputs
__device__ float d_a   [256];
__device__ float d_X   [1048576];
__device__ float d_H1  [1048576];
__device__ float d_H2  [1048576];
__device__ float d_d1  [16384];
// ---------------- fp16 mirrors ----------------
__device__ __half g_h16[26214400];    // h
__device__ __half g_a16[26214400];    // attn out
__device__ __half g_t16[104857600];   // FF1 out
__device__ __half g_wq16[786432];
__device__ __half g_wo16[262144];
__device__ __half g_w116[1048576];
__device__ __half g_w216[1048576];

// ---------------- asm helpers ----------------
__device__ __forceinline__ uint32_t smem_u32(const void* p) {
    uint32_t a;
    asm("{ .reg .u64 t; cvta.to.shared.u64 t, %1; cvt.u32.u64 %0, t; }" : "=r"(a) : "l"(p));
    return a;
}
#define CP16(s, g) asm volatile("cp.async.cg.shared.global [%0], [%1], 16;" :: "r"(s), "l"(g))
#define CP_COMMIT() asm volatile("cp.async.commit_group;")
#define CP_WAIT(n)  asm volatile("cp.async.wait_group %0;" :: "n"(n) : "memory")
#define LDSM_X4(r0,r1,r2,r3,addr) \
    asm volatile("ldmatrix.sync.aligned.m8n8.x4.shared.b16 {%0,%1,%2,%3}, [%4];" \
        : "=r"(r0),"=r"(r1),"=r"(r2),"=r"(r3) : "r"(addr))
#define LDSM_X2(r0,r1,addr) \
    asm volatile("ldmatrix.sync.aligned.m8n8.x2.shared.b16 {%0,%1}, [%2];" \
        : "=r"(r0),"=r"(r1) : "r"(addr))
#define MMAH16(c0,c1,c2,c3,a0,a1,a2,a3,b0,b1) \
    asm volatile("mma.sync.aligned.m16n8k16.row.col.f32.f16.f16.f32 " \
        "{%0,%1,%2,%3},{%4,%5,%6,%7},{%8,%9},{%0,%1,%2,%3};" \
        : "+f"(c0),"+f"(c1),"+f"(c2),"+f"(c3) \
        : "r"(a0),"r"(a1),"r"(a2),"r"(a3),"r"(b0),"r"(b1))

// ============================================================================
// fp16 GEMM (fp32 accum): C(MxN) = A(MxK) @ B(NxK)^T + bias
// CTA 128x128, BK=32, 8 warps (2x4), warp tile 64x32. 2-stage cp.async,
// smem stride 40 halves (conflict-free ldmatrix). 2 CTAs/SM.
// Output: fp32 Cmat and/or fp16 Chalf (with optional relu).
// ============================================================================
#define HSTR    40
#define TILE_H  (128*HSTR*2)      // 10240 bytes per tile
#define STAGE_H (2*TILE_H)        // 20480 per stage
#define GSMEM   (2*STAGE_H)       // 40960 bytes

__global__ __launch_bounds__(256, 2) void k_gemm_h(
    const __half* __restrict__ A, const __half* __restrict__ B,
    const float* __restrict__ bias,
    float* __restrict__ Cmat, __half* __restrict__ Chalf,
    int M, int N, int K, int relu) {
    extern __shared__ __align__(128) char smem[];
    uint32_t sb = smem_u32(smem);

    const int tid = threadIdx.x, lane = tid & 31, wid = tid >> 5;
    const int wm = wid >> 2, wn = wid & 3;            // 2x4 warp grid
    const int gid = lane >> 2, tig = lane & 3;
    const int m0 = blockIdx.y * 128, n0 = blockIdx.x * 128;

    float acc[4][4][4];
#pragma unroll
    for (int a = 0; a < 4; a++)
#pragma unroll
        for (int b = 0; b < 4; b++)
#pragma unroll
            for (int c = 0; c < 4; c++) acc[a][b][c] = 0.f;

    // ldmatrix lane-relative offsets (halves)
    const uint32_t a_row = (uint32_t)(lane & 15);
    const uint32_t a_cg  = (uint32_t)((lane >> 4) * 8);
    const uint32_t b_row = (uint32_t)(lane & 7);
    const uint32_t b_cg  = (uint32_t)(((lane >> 3) & 1) * 8);

    const int nch = K >> 5;      // K / 32

    // stage one 128x32 half chunk of A and B: 512 16B-slots per tile, 2/thread
#define STAGE_CHUNK(stg, k0)                                                   \
    do {                                                                       \
        uint32_t sA = sb + (uint32_t)((stg)*STAGE_H);                          \
        uint32_t sB = sA + (uint32_t)TILE_H;                                   \
        _Pragma("unroll")                                                      \
        for (int i = 0; i < 2; i++) {                                          \
            int idx = tid + i * 256;      /* 0..511 */                         \
            int r = idx >> 2, c8 = idx & 3;                                    \
            uint32_t soff = (uint32_t)(r * HSTR + c8 * 8) * 2;                 \
            CP16(sA + soff, A + (size_t)(m0 + r) * K + (k0) + c8 * 8);         \
            CP16(sB + soff, B + (size_t)(n0 + r) * K + (k0) + c8 * 8);         \
        }                                                                      \
        CP_COMMIT();                                                           \
    } while (0)

    STAGE_CHUNK(0, 0);

    for (int ch = 0; ch < nch; ch++) {
        if (ch + 1 < nch) STAGE_CHUNK((ch + 1) & 1, (ch + 1) << 5);
        if (ch + 1 < nch) CP_WAIT(1); else CP_WAIT(0);
        __syncthreads();

        uint32_t sA = sb + (uint32_t)((ch & 1)*STAGE_H);
        uint32_t sB = sA + (uint32_t)TILE_H;

#pragma unroll
        for (int kk = 0; kk < 2; kk++) {
            uint32_t bf[4][2];
#pragma unroll
            for (int nt = 0; nt < 4; nt++) {
                uint32_t addr = sB + ((uint32_t)(wn*32 + nt*8 + b_row)*HSTR
                                      + kk*16 + b_cg) * 2;
                LDSM_X2(bf[nt][0], bf[nt][1], addr);
            }
#pragma unroll
            for (int mt = 0; mt < 4; mt++) {
                uint32_t addr = sA + ((uint32_t)(wm*64 + mt*16 + a_row)*HSTR
                                      + kk*16 + a_cg) * 2;
                uint32_t a0, a1, a2, a3;
                LDSM_X4(a0, a1, a2, a3, addr);
#pragma unroll
                for (int nt = 0; nt < 4; nt++) {
                    MMAH16(acc[mt][nt][0], acc[mt][nt][1], acc[mt][nt][2], acc[mt][nt][3],
                           a0, a1, a2, a3, bf[nt][0], bf[nt][1]);
                }
            }
        }
        __syncthreads();
    }
#undef STAGE_CHUNK

    // epilogue
#pragma unroll
    for (int mt = 0; mt < 4; mt++) {
#pragma unroll
        for (int nt = 0; nt < 4; nt++) {
            int row = m0 + wm*64 + mt*16 + gid;
            int col = n0 + wn*32 + nt*8 + tig*2;
            float b0 = bias[col], b1 = bias[col + 1];
            float v00 = acc[mt][nt][0] + b0, v01 = acc[mt][nt][1] + b1;
            float v10 = acc[mt][nt][2] + b0, v11 = acc[mt][nt][3] + b1;
            if (relu) {
                v00 = fmaxf(v00, 0.f); v01 = fmaxf(v01, 0.f);
                v10 = fmaxf(v10, 0.f); v11 = fmaxf(v11, 0.f);
            }
            if (Cmat) {
                *reinterpret_cast<float2*>(Cmat + (size_t)row*N + col)     = make_float2(v00, v01);
                *reinterpret_cast<float2*>(Cmat + (size_t)(row+8)*N + col) = make_float2(v10, v11);
            }
            if (Chalf) {
                *reinterpret_cast<__half2*>(Chalf + (size_t)row*N + col)     = __floats2half2_rn(v00, v01);
                *reinterpret_cast<__half2*>(Chalf + (size_t)(row+8)*N + col) = __floats2half2_rn(v10, v11);
            }
        }
    }
}

// ---------------- weight fp32 -> fp16 ----------------
__global__ void k_cvth(const float* __restrict__ in, __half* __restrict__ outp, int n) {
    int i = blockIdx.x*256 + threadIdx.x;
    if (i < n) outp[i] = __float2half(in[i]);
}

// ---------------- embedding ----------------
__global__ void k_embed(const float* __restrict__ x, const float* __restrict__ Wfc,
                        const float* __restrict__ bfc, const float* __restrict__ cls,
                        const float* __restrict__ pos, float* __restrict__ hout,
                        __half* __restrict__ h16) {
    int r = blockIdx.x;
    int s = r / L, l = r % L;
    int b = s >> 4, c = s & 15;
    int o = threadIdx.x;
    float v;
    if (l < T) {
        const float* xr = x + (((size_t)(b*T + l))*C + c)*INF_;
        const float* wr = Wfc + o*INF_;
        float acc = bfc[o];
#pragma unroll
        for (int i = 0; i < INF_; i++) acc += xr[i]*wr[i];
        v = acc;
    } else {
        v = cls[((l - T)*C + c)*H + o];
    }
    v += pos[(l*C + c)*H + o];
    size_t idx = (size_t)r*H + o;
    hout[idx] = v;
    h16[idx] = __float2half(v);
}

// ---------------- graph constructor ----------------
__global__ void k_graph(const float* __restrict__ emb1, const float* __restrict__ emb2,
                        const float* __restrict__ Wl1, const float* __restrict__ bl1,
                        const float* __restrict__ Wl2, const float* __restrict__ bl2,
                        float* __restrict__ a_out) {
    __shared__ float sm1[16][256];
    __shared__ float sm2[16][256];
    int o = threadIdx.x;
    for (int c = 0; c < 16; c++) {
        float s1 = bl1[o], s2 = bl2[o];
        const float* e1 = emb1 + c*256;
        const float* e2 = emb2 + c*256;
        const float* w1 = Wl1 + o*256;
        const float* w2 = Wl2 + o*256;
        for (int i = 0; i < 256; i++) { s1 += e1[i]*w1[i]; s2 += e2[i]*w2[i]; }
        sm1[c][o] = tanhf(s1); sm2[c][o] = tanhf(s2);
    }
    __syncthreads();
    int v = o >> 4, w = o & 15;
    float s = 0.f;
    for (int k = 0; k < 256; k++) s += sm1[v][k]*sm2[w][k] - sm2[v][k]*sm1[w][k];
    float adj = fmaxf(tanhf(s), 0.f) + ((v == w) ? 1.f : 0.f);
    __shared__ float sadj[256];
    __shared__ float srow[16];
    sadj[o] = adj;
    __syncthreads();
    if (o < 16) {
        float rs = 0.f;
        for (int j = 0; j < 16; j++) rs += sadj[o*16 + j];
        srow[o] = rs;
    }
    __syncthreads();
    a_out[o] = sadj[o] / srow[v];
}

// ---------------- fused attention (fp16 output) ----------------
__global__ void k_attn(const float* __restrict__ qkv, __half* __restrict__ out) {
    int hh = blockIdx.x;
    int s  = blockIdx.y;
    int tid = threadIdx.x;
    __shared__ float Ks[100][32];
    __shared__ float Vs[100][32];
    const float* base = qkv + (size_t)s*L*768;
    for (int idx = tid; idx < L*DH; idx += 128) {
        int l = idx >> 5, d = idx & 31;
        Ks[l][d] = base[l*768 + 256 + hh*DH + d];
        Vs[l][d] = base[l*768 + 512 + hh*DH + d];
    }
    __syncthreads();
    if (tid < L) {
        int lq = tid;
        float q[DH];
        const float* qp = base + lq*768 + hh*DH;
#pragma unroll
        for (int d = 0; d < DH; d++) q[d] = qp[d] * 0.17677669529663687f;
        int kmax = (lq >= T) ? L : (lq + 1);
        float m = -1e30f, sum = 0.f;
        float acc[DH];
#pragma unroll
        for (int d = 0; d < DH; d++) acc[d] = 0.f;
        for (int k = 0; k < kmax; k++) {
            float sc = 0.f;
#pragma unroll
            for (int d = 0; d < DH; d++) sc += q[d]*Ks[k][d];
            float mn = fmaxf(m, sc);
            float corr = expf(m - mn);
            float pr   = expf(sc - mn);
            sum = sum*corr + pr;
#pragma unroll
            for (int d = 0; d < DH; d++) acc[d] = acc[d]*corr + pr*Vs[k][d];
            m = mn;
        }
        float inv = 1.f/sum;
        __half* op = out + ((size_t)s*L + lq)*H + hh*DH;
#pragma unroll
        for (int d = 0; d < DH; d++) op[d] = __float2half(acc[d]*inv);
    }
}

// ---------------- residual add + LayerNorm (warp/row; fp32 h + fp16 mirror) --
__global__ __launch_bounds__(256) void k_addln(
        float* __restrict__ h, const float* __restrict__ p,
        const float* __restrict__ g, const float* __restrict__ b,
        __half* __restrict__ h16) {
    int w = threadIdx.x >> 5, lane = threadIdx.x & 31;
    int r = blockIdx.x*8 + w;
    float4* h4 = reinterpret_cast<float4*>(h + (size_t)r*H);
    const float4* p4 = reinterpret_cast<const float4*>(p + (size_t)r*H);
    float4 v0 = h4[lane], v1 = h4[lane + 32];
    float4 q0 = p4[lane], q1 = p4[lane + 32];
    v0.x += q0.x; v0.y += q0.y; v0.z += q0.z; v0.w += q0.w;
    v1.x += q1.x; v1.y += q1.y; v1.z += q1.z; v1.w += q1.w;
    float s = v0.x + v0.y + v0.z + v0.w + v1.x + v1.y + v1.z + v1.w;
#pragma unroll
    for (int off = 16; off > 0; off >>= 1) s += __shfl_xor_sync(0xffffffffu, s, off);
    float mean = s * (1.f/H);
    float d0x = v0.x-mean, d0y = v0.y-mean, d0z = v0.z-mean, d0w = v0.w-mean;
    float d1x = v1.x-mean, d1y = v1.y-mean, d1z = v1.z-mean, d1w = v1.w-mean;
    float vs = d0x*d0x + d0y*d0y + d0z*d0z + d0w*d0w
             + d1x*d1x + d1y*d1y + d1z*d1z + d1w*d1w;
#pragma unroll
    for (int off = 16; off > 0; off >>= 1) vs += __shfl_xor_sync(0xffffffffu, vs, off);
    float rstd = rsqrtf(vs * (1.f/H) + 1e-5f);
    const float4* g4 = reinterpret_cast<const float4*>(g);
    const float4* b4 = reinterpret_cast<const float4*>(b);
    float4 ga = g4[lane], gb = g4[lane + 32];
    float4 ba = b4[lane], bb = b4[lane + 32];
    float4 o0, o1;
    o0.x = d0x*rstd*ga.x + ba.x; o0.y = d0y*rstd*ga.y + ba.y;
    o0.z = d0z*rstd*ga.z + ba.z; o0.w = d0w*rstd*ga.w + ba.w;
    o1.x = d1x*rstd*gb.x + bb.x; o1.y = d1y*rstd*gb.y + bb.y;
    o1.z = d1z*rstd*gb.z + bb.z; o1.w = d1w*rstd*gb.w + bb.w;
    h4[lane] = o0; h4[lane + 32] = o1;
    __half2* hh2 = reinterpret_cast<__half2*>(h16 + (size_t)r*H);
    hh2[lane*2]      = __floats2half2_rn(o0.x, o0.y);
    hh2[lane*2+1]    = __floats2half2_rn(o0.z, o0.w);
    hh2[64 + lane*2] = __floats2half2_rn(o1.x, o1.y);
    hh2[65 + lane*2] = __floats2half2_rn(o1.z, o1.w);
}

// ---------------- mixprop pieces ----------------
__global__ void k_extract(const float* __restrict__ h, float* __restrict__ X) {
    int b = blockIdx.x;
    int ch = threadIdx.x;
    int lc = b & 3, sw = b >> 2;
    X[(size_t)b*H + ch] = h[(size_t)sw*(L*H) + (T + lc)*H + ch];
}

__global__ void k_prop(const float* __restrict__ a, const float* __restrict__ in,
                       float* __restrict__ out) {
    __shared__ float sa[256];
    int tid = threadIdx.x;
    sa[tid] = a[tid];
    __syncthreads();
    int b = blockIdx.x;
    int lc = b & 3, v = (b >> 2) & 15, n = b >> 6;
    float acc = 0.f;
#pragma unroll
    for (int w = 0; w < 16; w++)
        acc += sa[v*16 + w] * in[((size_t)(n*16 + w)*4 + lc)*H + tid];
    out[(size_t)b*H + tid] = acc;
}

__global__ void k_mixout(const float* __restrict__ X, const float* __restrict__ H1,
                         const float* __restrict__ H2, const float* __restrict__ Wm,
                         const float* __restrict__ bm, float* __restrict__ h,
                         __half* __restrict__ h16) {
    __shared__ float row[768];
    int b = blockIdx.x, o = threadIdx.x;
    row[o]       = X [(size_t)b*H + o];
    row[256 + o] = H1[(size_t)b*H + o];
    row[512 + o] = H2[(size_t)b*H + o];
    __syncthreads();
    const float* wr = Wm + (size_t)o*768;
    float acc = bm[o];
    for (int ch = 0; ch < 768; ch++) acc += wr[ch]*row[ch];
    int lc = b & 3, sw = b >> 2;
    size_t idx = (size_t)sw*(L*H) + (T + lc)*H + o;
    h[idx] = acc;
    h16[idx] = __float2half(acc);
}

// ---------------- decoder ----------------
__global__ void k_dec1(const float* __restrict__ h, const float* __restrict__ Wd1,
                       const float* __restrict__ bd1, float* __restrict__ d1) {
    __shared__ float zc[1024];
    int n = blockIdx.x, o = threadIdx.x;
    float acc = 0.f;
    for (int c = 0; c < 16; c++) {
        const float* hp = h + (size_t)(n*16 + c)*(L*H) + T*H;
        for (int jj = o; jj < 1024; jj += 256) zc[jj] = tanhf(hp[jj]);
        __syncthreads();
        const float* wr = Wd1 + (size_t)o*16384 + c*1024;
        float a = 0.f;
        for (int jj = 0; jj < 1024; jj++) a += wr[jj]*zc[jj];
        acc += a;
        __syncthreads();
    }
    acc += bd1[o];
    d1[n*H + o] = 0.5f*acc*(1.f + erff(acc*0.70710678118654752f));
}

__global__ void k_dec2(const float* __restrict__ d1, const float* __restrict__ Wd2,
                       const float* __restrict__ bd2, float* __restrict__ out) {
    int n = blockIdx.x, tid = threadIdx.x;
    float v = d1[n*H + tid]*Wd2[tid];
    __shared__ float red[8];
#pragma unroll
    for (int off = 16; off > 0; off >>= 1) v += __shfl_down_sync(0xffffffffu, v, off);
    if ((tid & 31) == 0) red[tid >> 5] = v;
    __syncthreads();
    if (tid == 0) {
        float s = 0.f;
        for (int i = 0; i < 8; i++) s += red[i];
        out[n] = s + bd2[0];
    }
}

// ---------------- launch ----------------
extern "C" void kernel_launch(void* const* d_in, const int* in_sizes, int n_in,
                              void* d_out, int out_size) {
    const float* x        = (const float*)d_in[0];
    const float* Wfc      = (const float*)d_in[3];
    const float* bfc      = (const float*)d_in[4];
    const float* cls_tok  = (const float*)d_in[5];
    const float* pos_emb  = (const float*)d_in[6];
    const float* emb1     = (const float*)d_in[7];
    const float* emb2     = (const float*)d_in[8];
    const float* Wl1      = (const float*)d_in[9];
    const float* bl1      = (const float*)d_in[10];
    const float* Wl2      = (const float*)d_in[11];
    const float* bl2      = (const float*)d_in[12];
    const float* Wqkv     = (const float*)d_in[13];
    const float* bqkv     = (const float*)d_in[14];
    const float* Wo       = (const float*)d_in[15];
    const float* bo       = (const float*)d_in[16];
    const float* W1       = (const float*)d_in[17];
    const float* b1       = (const float*)d_in[18];
    const float* W2       = (const float*)d_in[19];
    const float* b2       = (const float*)d_in[20];
    const float* ln1g     = (const float*)d_in[21];
    const float* ln1b     = (const float*)d_in[22];
    const float* ln2g     = (const float*)d_in[23];
    const float* ln2b     = (const float*)d_in[24];
    const float* Wmlp     = (const float*)d_in[25];
    const float* bmlp     = (const float*)d_in[26];
    const float* Wd1      = (const float*)d_in[27];
    const float* bd1      = (const float*)d_in[28];
    const float* Wd2      = (const float*)d_in[29];
    const float* bd2      = (const float*)d_in[30];
    float* out = (float*)d_out;

    float *p_h, *p_qkv, *p_o, *p_a, *p_X, *p_H1, *p_H2, *p_d1;
    __half *p_h16, *p_a16, *p_t16, *p_wq16, *p_wo16, *p_w116, *p_w216;
    cudaGetSymbolAddress((void**)&p_h,    d_h);
    cudaGetSymbolAddress((void**)&p_qkv,  d_qkv);
    cudaGetSymbolAddress((void**)&p_o,    d_o);
    cudaGetSymbolAddress((void**)&p_a,    d_a);
    cudaGetSymbolAddress((void**)&p_X,    d_X);
    cudaGetSymbolAddress((void**)&p_H1,   d_H1);
    cudaGetSymbolAddress((void**)&p_H2,   d_H2);
    cudaGetSymbolAddress((void**)&p_d1,   d_d1);
    cudaGetSymbolAddress((void**)&p_h16,  g_h16);
    cudaGetSymbolAddress((void**)&p_a16,  g_a16);
    cudaGetSymbolAddress((void**)&p_t16,  g_t16);
    cudaGetSymbolAddress((void**)&p_wq16, g_wq16);
    cudaGetSymbolAddress((void**)&p_wo16, g_wo16);
    cudaGetSymbolAddress((void**)&p_w116, g_w116);
    cudaGetSymbolAddress((void**)&p_w216, g_w216);

    cudaFuncSetAttribute(k_gemm_h, cudaFuncAttributeMaxDynamicSharedMemorySize, GSMEM);

    // weights -> fp16 (once per launch)
    k_cvth<<<(786432 + 255)/256, 256>>>(Wqkv, p_wq16, 786432);
    k_cvth<<<(262144 + 255)/256, 256>>>(Wo,   p_wo16, 262144);
    k_cvth<<<(1048576 + 255)/256, 256>>>(W1,  p_w116, 1048576);
    k_cvth<<<(1048576 + 255)/256, 256>>>(W2,  p_w216, 1048576);

    // embedding + graph
    k_embed<<<M_ROWS, 256>>>(x, Wfc, bfc, cls_tok, pos_emb, p_h, p_h16);
    k_graph<<<1, 256>>>(emb1, emb2, Wl1, bl1, Wl2, bl2, p_a);

    for (int l = 0; l < LAYERS; l++) {
        if (l > 0) {
            k_extract<<<4096, 256>>>(p_h, p_X);
            k_prop<<<4096, 256>>>(p_a, p_X,  p_H1);
            k_prop<<<4096, 256>>>(p_a, p_H1, p_H2);
            k_mixout<<<4096, 256>>>(p_X, p_H1, p_H2,
                                    Wmlp + (size_t)(l-1)*256*768, bmlp + (l-1)*256,
                                    p_h, p_h16);
        }
        // QKV (fp32 out for softmax)
        k_gemm_h<<<dim3(768/128, M_ROWS/128), 256, GSMEM>>>(
            p_h16, p_wq16 + (size_t)l*768*256, bqkv + l*768,
            p_qkv, nullptr, M_ROWS, 768, 256, 0);
        // attention -> fp16
        k_attn<<<dim3(NH, SEQS), 128>>>(p_qkv, p_a16);
        // O-proj (fp32 out -> addln)
        k_gemm_h<<<dim3(256/128, M_ROWS/128), 256, GSMEM>>>(
            p_a16, p_wo16 + (size_t)l*256*256, bo + l*256,
            p_o, nullptr, M_ROWS, 256, 256, 0);
        k_addln<<<M_ROWS/8, 256>>>(p_h, p_o, ln1g + l*256, ln1b + l*256, p_h16);
        // FF1 (relu, fp16 out -> FF2)
        k_gemm_h<<<dim3(1024/128, M_ROWS/128), 256, GSMEM>>>(
            p_h16, p_w116 + (size_t)l*1024*256, b1 + l*1024,
            nullptr, p_t16, M_ROWS, 1024, 256, 1);
        // FF2 (fp32 out -> addln)
        k_gemm_h<<<dim3(256/128, M_ROWS/128), 256, GSMEM>>>(
            p_t16, p_w216 + (size_t)l*256*1024, b2 + l*256,
            p_o, nullptr, M_ROWS, 256, 1024, 0);
        k_addln<<<M_ROWS/8, 256>>>(p_h, p_o, ln2g + l*256, ln2b + l*256, p_h16);
    }

    // decoder
    k_dec1<<<BS, 256>>>(p_h, Wd1, bd1, p_d1);
    k_dec2<<<BS, 256>>>(p_d1, Wd2, bd2, out);
}